// round 17
// baseline (speedup 1.0000x reference)
#include <cuda_runtime.h>
#include <cuda_fp16.h>
#include <math.h>

#define EPS      1e-5f
#define LSEQ     32
#define DM       128
#define CIN      96
#define COUT     12
#define DIN      256
#define DST      16
#define NH       8
#define CDIM     288          // DIN + 2*DST
#define EPROJ    552
#define ESTR     584          // zx row stride (72 n-tiles)
#define TST      36           // hs transposed stride
#define NT       256
#define MAXB     1024
#define THALF    16

#define IP_NT    72
#define IP_KC    8
#define OP_NT    16
#define OP_KC    16
#define FI_KC    6

typedef unsigned long long u64;

// device scratch: fp16 hi/lo fragment-packed weights
#define IPF_N (4 * IP_NT * IP_KC * 128)
#define OPF_N (4 * OP_NT * OP_KC * 128)
#define FIF_N (16 * FI_KC * 128)
__device__ unsigned g_ipf[IPF_N];
__device__ unsigned g_opf[OPF_N];
__device__ unsigned g_fif[FIF_N];
__device__ float g_A[(size_t)MAXB * 2 * DM];

// shared memory layout (floats) — 3 CTAs/SM
#define OFF_ZX    0                      // 16*584 = 9344 (stage0 buf + fc_in staging overlay)
#define OFF_HST   9344                   // 128*36 = 4608
#define OFF_APK   (OFF_HST + DM*TST)     // 2048 words (in_proj A-pack)
#define OFF_DT    (OFF_APK + 2048)       // 128
#define OFF_DA    (OFF_DT + 128)         // 128
#define OFF_INV   (OFF_DA + 128)         // 32
#define OFF_INV2  (OFF_INV + 32)         // 16
#define OFF_RED   (OFF_INV2 + 16)        // 256
#define OFF_CARRY (OFF_RED + NT)         // 3*288 = 864
#define SMEM_FLOATS (OFF_CARRY + 864)    // 17424 floats = 69696 B

// packed out_proj A words in dead z cols of zx: word w -> row w>>8, col w&255
#define ZIDX(w) ((((w) >> 8) * ESTR) + ((w) & 255))
#define FI_STAGE 4096   // fc_in staging word offset inside zx region

__device__ __forceinline__ float sigmoidf_(float v) {
    return 1.f / (1.f + __expf(-v));
}
__device__ __forceinline__ u64 pk2(float lo, float hi) {
    u64 r; asm("mov.b64 %0,{%1,%2};" : "=l"(r) : "f"(lo), "f"(hi)); return r;
}
__device__ __forceinline__ u64 dup2(float v) { return pk2(v, v); }
__device__ __forceinline__ void upk2(u64 a, float& lo, float& hi) {
    asm("mov.b64 {%0,%1},%2;" : "=f"(lo), "=f"(hi) : "l"(a));
}
__device__ __forceinline__ u64 fma2_(u64 a, u64 b, u64 c) {
    u64 d; asm("fma.rn.f32x2 %0,%1,%2,%3;" : "=l"(d) : "l"(a), "l"(b), "l"(c)); return d;
}
__device__ __forceinline__ u64 mul2_(u64 a, u64 b) {
    u64 d; asm("mul.rn.f32x2 %0,%1,%2;" : "=l"(d) : "l"(a), "l"(b)); return d;
}
__device__ __forceinline__ unsigned hcvt(float v0, float v1) {
    unsigned r;
    asm("cvt.rn.f16x2.f32 %0,%1,%2;" : "=r"(r) : "f"(v1), "f"(v0));
    return r;
}
__device__ __forceinline__ void hsplit(float v0, float v1, unsigned& hi, unsigned& lo) {
    hi = hcvt(v0, v1);
    __half2 h = *reinterpret_cast<__half2*>(&hi);
    float h0 = __low2float(h), h1 = __high2float(h);
    lo = hcvt(v0 - h0, v1 - h1);
}
__device__ __forceinline__ void mma_f16(float* d, const unsigned* a,
                                        unsigned b0, unsigned b1) {
    asm volatile(
        "mma.sync.aligned.m16n8k16.row.col.f32.f16.f16.f32 "
        "{%0,%1,%2,%3},{%4,%5,%6,%7},{%8,%9},{%0,%1,%2,%3};"
        : "+f"(d[0]), "+f"(d[1]), "+f"(d[2]), "+f"(d[3])
        : "r"(a[0]), "r"(a[1]), "r"(a[2]), "r"(a[3]), "r"(b0), "r"(b1));
}

// ---- prep: fold norms, fp16 hi/lo split, B-fragment lane order --------------
__global__ void prep_weights(const float* __restrict__ ipw,
                             const float* __restrict__ bnw,
                             const float* __restrict__ opw,
                             const float* __restrict__ mnw,
                             const float* __restrict__ fiw) {
    int i = blockIdx.x * blockDim.x + threadIdx.x;
    if (i < IPF_N) {
        int blk = i / (IP_NT * IP_KC * 128);
        int r   = i - blk * (IP_NT * IP_KC * 128);
        int n   = r / (IP_KC * 128);
        int q   = r - n * (IP_KC * 128);
        int kc  = q >> 7;
        int rem = q & 127;
        int lane = rem >> 2, comp = rem & 3;
        int g = lane >> 2, c = lane & 3;
        int e  = n * 8 + g;
        int k0 = kc * 16 + 2 * c + ((comp & 1) ? 8 : 0);
        float v0 = 0.f, v1 = 0.f;
        if (e < EPROJ) {
            v0 = ipw[((size_t)blk * EPROJ + e) * DM + k0]     * bnw[blk * DM + k0];
            v1 = ipw[((size_t)blk * EPROJ + e) * DM + k0 + 1] * bnw[blk * DM + k0 + 1];
        }
        unsigned hi, lo;
        hsplit(v0, v1, hi, lo);
        g_ipf[i] = (comp < 2) ? hi : lo;
    } else if (i < IPF_N + OPF_N) {
        int j   = i - IPF_N;
        int blk = j >> 15;
        int r   = j & 32767;
        int n   = r >> 11;
        int q   = r & 2047;
        int kc  = q >> 7;
        int rem = q & 127;
        int lane = rem >> 2, comp = rem & 3;
        int g = lane >> 2, c = lane & 3;
        int d  = n * 8 + g;
        int e0 = kc * 16 + 2 * c + ((comp & 1) ? 8 : 0);
        float v0 = opw[((size_t)blk * DM + d) * DIN + e0]     * mnw[blk * DIN + e0];
        float v1 = opw[((size_t)blk * DM + d) * DIN + e0 + 1] * mnw[blk * DIN + e0 + 1];
        unsigned hi, lo;
        hsplit(v0, v1, hi, lo);
        g_opf[j] = (comp < 2) ? hi : lo;
    } else if (i < IPF_N + OPF_N + FIF_N) {
        int j   = i - IPF_N - OPF_N;
        int n   = j / (FI_KC * 128);
        int q   = j - n * (FI_KC * 128);
        int kc  = q >> 7;
        int rem = q & 127;
        int lane = rem >> 2, comp = rem & 3;
        int g = lane >> 2, c = lane & 3;
        int d  = n * 8 + g;
        int k0 = kc * 16 + 2 * c + ((comp & 1) ? 8 : 0);
        float v0 = fiw[d * CIN + k0];
        float v1 = fiw[d * CIN + k0 + 1];
        unsigned hi, lo;
        hsplit(v0, v1, hi, lo);
        g_fif[j] = (comp < 2) ? hi : lo;
    }
}

// ---- finalize ----------------------------------------------------------------
__global__ void finalize_kernel(const float* __restrict__ fow,
                                const float* __restrict__ fob,
                                const float* __restrict__ olw,
                                const float* __restrict__ olb,
                                float* __restrict__ out, int B) {
    int idx = blockIdx.x * blockDim.x + threadIdx.x;
    if (idx >= B * COUT) return;
    int b = idx / COUT, o = idx - b * COUT;
    float Swl = 0.f;
#pragma unroll
    for (int t = 0; t < LSEQ; t++) Swl += olw[t];
    const float* A0 = g_A + (size_t)b * 2 * DM;
    float acc = 0.f;
#pragma unroll 4
    for (int d = 0; d < DM; d++) acc = fmaf(fow[o * DM + d], A0[d] + A0[DM + d], acc);
    out[idx] = acc + fob[o] * Swl + olb[0];
}

// ---- main: one CTA per (batch, direction), t processed in halves --------------
__global__ void __launch_bounds__(NT, 3) mamba_actor_kernel(
    const float* __restrict__ x,        // (B, 96)
    const float* __restrict__ buffer,   // (B, 96, 32)
    const float* __restrict__ fib,      // (128,)
    const float* __restrict__ cw,       // (4, 288, 4)
    const float* __restrict__ cb,       // (4, 288)
    const float* __restrict__ dtb,      // (4, 8)
    const float* __restrict__ alog,     // (4, 8)
    const float* __restrict__ Dp,       // (4, 8)
    const float* __restrict__ nfw,      // (2, 128)
    const float* __restrict__ olw,      // (1, 32)
    float* __restrict__ out)
{
    extern __shared__ float sm[];
    float*    s_zx    = sm + OFF_ZX;    // [t_local][e], stride ESTR (16 rows)
    unsigned* s_zxw   = reinterpret_cast<unsigned*>(sm + OFF_ZX);
    float*    s_buf   = sm + OFF_ZX;    // stage0/fc_in input overlay
    float*    s_hsT   = sm + OFF_HST;   // [d][t global], stride TST
    unsigned* s_apk   = reinterpret_cast<unsigned*>(sm + OFF_APK);
    float*    s_dt    = sm + OFF_DT;    // [t_local][h]
    float*    s_dA    = sm + OFF_DA;
    float*    s_inv   = sm + OFF_INV;   // 32 (final) / 16 (per-half)
    float*    s_inv2  = sm + OFF_INV2;  // 16
    float*    s_red   = sm + OFF_RED;
    float*    s_carry = sm + OFF_CARRY; // [CDIM][3] conv carry

    const int B    = gridDim.x >> 1;
    const int b    = blockIdx.x >> 1;
    const int dir  = blockIdx.x & 1;
    const int tid  = threadIdx.x;
    const int lane = tid & 31;
    const int warp = tid >> 5;
    const int kb   = lane & 3;
    const int tb   = lane >> 2;

    // ---- Stage 0: shifted buffer -> smem (dir-flipped, [c][t]) + buf output --
    {
        const float* bsrc = buffer + (size_t)b * CIN * LSEQ;
        const float* xsrc = x + (size_t)b * CIN;
        float* bdst = out + (size_t)B * COUT + (size_t)b * CIN * LSEQ;
        for (int idx = tid; idx < CIN * LSEQ; idx += NT) {
            int c = idx >> 5, l = idx & 31;
            float v = (l < LSEQ - 1) ? bsrc[c * LSEQ + l + 1] : xsrc[c];
            int ls = dir ? (LSEQ - 1 - l) : l;
            s_buf[c * LSEQ + ls] = v;
            if (dir == 0) bdst[idx] = v;
        }
    }
    __syncthreads();

    // ---- fc_in A pack: buf fragments -> fp16 words at FI_STAGE ----------------
    {
#pragma unroll
        for (int kk = 0; kk < 2; kk++) {
            int km = (kk == 0) ? warp : (8 + warp);
            if (kk == 0 || warp < 4) {
                int kc = km >> 1, m = km & 1;
#pragma unroll
                for (int r = 0; r < 4; r++) {
                    int tt = m * 16 + tb + (r & 1) * 8;
                    int k  = kc * 16 + 2 * kb + (r >> 1) * 8;
                    float v0 = s_buf[k * LSEQ + tt];
                    float v1 = s_buf[(k + 1) * LSEQ + tt];
                    s_zxw[FI_STAGE + km * 128 + lane * 4 + r] = hcvt(v0, v1);
                }
            }
        }
    }
    __syncthreads();

    // ---- fc_in via fp16 tensor cores (2-pass) + fused in_proj A-pack ---------
    {
        float dacc[2][2][4];
#pragma unroll
        for (int j = 0; j < 2; j++)
#pragma unroll
            for (int m = 0; m < 2; m++)
#pragma unroll
                for (int q = 0; q < 4; q++) dacc[j][m][q] = 0.f;
#pragma unroll
        for (int kc = 0; kc < FI_KC; kc++) {
            uint4 ah[2];
#pragma unroll
            for (int m = 0; m < 2; m++)
                ah[m] = *reinterpret_cast<const uint4*>(
                    s_zxw + FI_STAGE + (kc * 2 + m) * 128 + lane * 4);
            uint4 bf0 = *reinterpret_cast<const uint4*>(
                g_fif + ((size_t)((warp * 2 + 0) * FI_KC + kc)) * 128 + lane * 4);
            uint4 bf1 = *reinterpret_cast<const uint4*>(
                g_fif + ((size_t)((warp * 2 + 1) * FI_KC + kc)) * 128 + lane * 4);
            mma_f16(dacc[0][0], &ah[0].x, bf0.x, bf0.y);
            mma_f16(dacc[0][1], &ah[1].x, bf0.x, bf0.y);
            mma_f16(dacc[1][0], &ah[0].x, bf1.x, bf1.y);
            mma_f16(dacc[1][1], &ah[1].x, bf1.x, bf1.y);
            mma_f16(dacc[0][0], &ah[0].x, bf0.z, bf0.w);
            mma_f16(dacc[0][1], &ah[1].x, bf0.z, bf0.w);
            mma_f16(dacc[1][0], &ah[0].x, bf1.z, bf1.w);
            mma_f16(dacc[1][1], &ah[1].x, bf1.z, bf1.w);
        }
#pragma unroll
        for (int j = 0; j < 2; j++) {
            int n  = warp * 2 + j;
            int d0 = n * 8 + 2 * kb;
            float f0 = fib[d0], f1 = fib[d0 + 1];
            unsigned wb = (((n >> 1) * 2) * 128) + lane * 4 + 2 * (n & 1);
#pragma unroll
            for (int m = 0; m < 2; m++) {
                int t0 = m * 16 + tb;
                float v0 = dacc[j][m][0] + f0;
                float v1 = dacc[j][m][1] + f1;
                float v2 = dacc[j][m][2] + f0;
                float v3 = dacc[j][m][3] + f1;
                s_hsT[d0 * TST + t0]           = v0;
                s_hsT[(d0 + 1) * TST + t0]     = v1;
                s_hsT[d0 * TST + t0 + 8]       = v2;
                s_hsT[(d0 + 1) * TST + t0 + 8] = v3;
                s_apk[wb + m * 128 + 0] = hcvt(v0, v1);
                s_apk[wb + m * 128 + 1] = hcvt(v2, v3);
            }
        }
    }
    __syncthreads();

    for (int l = 0; l < 2; l++) {
        const int blk = dir * 2 + l;

        u64 st2[NH];
#pragma unroll
        for (int n = 0; n < 8; n++) st2[n] = 0ull;
        const float dskip = Dp[blk * NH + (tid >> 5)];

        for (int m = 0; m < 2; m++) {
            // ---- block rmsnorm partials for this half's 16 t ------------------
            {
                int tl = lane & 15, hb = (lane >> 4) * 8;
                float s = 0.f;
#pragma unroll
                for (int q = 0; q < 8; q++) {
                    float v = s_hsT[(warp * 16 + hb + q) * TST + (m * 16 + tl)];
                    s += v * v;
                }
                s_red[warp * 32 + lane] = s;
            }
            __syncthreads();
            if (tid < 16) {
                float s = 0.f;
#pragma unroll
                for (int w = 0; w < 8; w++)
                    s += s_red[w * 32 + tid] + s_red[w * 32 + 16 + tid];
                s_inv[tid] = rsqrtf(s * (1.f / DM) + EPS);
            }
            __syncthreads();

            // ---- in_proj half (M=16, 2-pass, packed A, 72 tiles) --------------
            {
                const unsigned* Wf = g_ipf + (size_t)blk * (IP_NT * IP_KC * 128);
                float dacc[9][4];
#pragma unroll
                for (int j = 0; j < 9; j++)
#pragma unroll
                    for (int q = 0; q < 4; q++) dacc[j][q] = 0.f;

#pragma unroll 1
                for (int kc = 0; kc < IP_KC; kc++) {
                    uint4 ah = *reinterpret_cast<const uint4*>(
                        s_apk + (kc * 2 + m) * 128 + lane * 4);
#pragma unroll
                    for (int jg = 0; jg < 3; jg++) {
                        uint4 bf[3];
#pragma unroll
                        for (int u = 0; u < 3; u++) {
                            int n = warp + (jg * 3 + u) * 8;
                            bf[u] = *reinterpret_cast<const uint4*>(
                                Wf + ((size_t)(n * IP_KC + kc)) * 128 + lane * 4);
                        }
#pragma unroll
                        for (int u = 0; u < 3; u++)
                            mma_f16(dacc[jg * 3 + u], &ah.x, bf[u].x, bf[u].y);
#pragma unroll
                        for (int u = 0; u < 3; u++)
                            mma_f16(dacc[jg * 3 + u], &ah.x, bf[u].z, bf[u].w);
                    }
                }
                // epilogue: scale by inv, store to zx (local rows tb, tb+8)
#pragma unroll
                for (int j = 0; j < 9; j++) {
                    int n = warp + j * 8;
                    float i0 = s_inv[tb], i1 = s_inv[tb + 8];
                    int e0 = n * 8 + 2 * kb;
                    float2 v0 = make_float2(dacc[j][0] * i0, dacc[j][1] * i0);
                    float2 v1 = make_float2(dacc[j][2] * i1, dacc[j][3] * i1);
                    *reinterpret_cast<float2*>(s_zx + tb * ESTR + e0) = v0;
                    *reinterpret_cast<float2*>(s_zx + (tb + 8) * ESTR + e0) = v1;
                }
            }
            __syncthreads();

            // ---- dt/dA for this half (128 threads = 16 t * 8 h) ---------------
            if (tid < 128) {
                int tl = tid >> 3, h = tid & 7;
                float v  = s_zx[tl * ESTR + DIN + CDIM + h] + dtb[blk * NH + h];
                float sp = (v > 20.f) ? v : log1pf(__expf(v));
                s_dt[tl * NH + h] = sp;
                s_dA[tl * NH + h] = __expf(-__expf(alog[blk * NH + h]) * sp);
            }
            __syncthreads();

            // ---- causal depthwise conv (k=4) + silu, carry across halves ------
            for (int c = tid; c < CDIM; c += NT) {
                float4 w4 = *reinterpret_cast<const float4*>(cw + ((size_t)blk * CDIM + c) * 4);
                float bb  = cb[blk * CDIM + c];
                float x0, x1, x2;
                if (m) { x0 = s_carry[c * 3]; x1 = s_carry[c * 3 + 1]; x2 = s_carry[c * 3 + 2]; }
                else   { x0 = 0.f; x1 = 0.f; x2 = 0.f; }
                float* col = s_zx + DIN + c;
#pragma unroll
                for (int tt = 0; tt < THALF; tt++) {
                    float xc = col[tt * ESTR];
                    float o  = fmaf(w4.x, x0, fmaf(w4.y, x1, fmaf(w4.z, x2, fmaf(w4.w, xc, bb))));
                    col[tt * ESTR] = o * sigmoidf_(o);
                    x0 = x1; x1 = x2; x2 = xc;
                }
                s_carry[c * 3] = x0; s_carry[c * 3 + 1] = x1; s_carry[c * 3 + 2] = x2;
            }
            __syncthreads();

            // ---- SSM scan half (+ fused gate): thread = (head, p) -------------
            {
                int h = tid >> 5;
                for (int tl = 0; tl < THALF; tl++) {
                    float* row = s_zx + tl * ESTR;
                    float dAv = s_dA[tl * NH + h];
                    float dtv = s_dt[tl * NH + h];
                    float xv  = row[DIN + tid];
                    u64 dA2  = dup2(dAv);
                    u64 dtx2 = dup2(dtv * xv);
                    const ulonglong2* Bp = reinterpret_cast<const ulonglong2*>(row + 2 * DIN);
                    const ulonglong2* Cp = reinterpret_cast<const ulonglong2*>(row + 2 * DIN + DST);
                    u64 y2 = 0ull;
#pragma unroll
                    for (int q = 0; q < 4; q++) {
                        ulonglong2 b2 = Bp[q];
                        ulonglong2 c2 = Cp[q];
                        st2[2*q]   = fma2_(st2[2*q],   dA2, mul2_(dtx2, b2.x));
                        y2         = fma2_(st2[2*q],   c2.x, y2);
                        st2[2*q+1] = fma2_(st2[2*q+1], dA2, mul2_(dtx2, b2.y));
                        y2         = fma2_(st2[2*q+1], c2.y, y2);
                    }
                    float ylo, yhi;
                    upk2(y2, ylo, yhi);
                    float yv = fmaf(dskip, xv, ylo + yhi);
                    float z  = row[tid];
                    row[DIN + tid] = yv * z * sigmoidf_(z);
                }
            }
            __syncthreads();

            // ---- mixer rmsnorm (16t x 16parts) + out_proj A pack ---------------
            {
                int tl = tid >> 4, part = tid & 15;
                const float4* gp = reinterpret_cast<const float4*>(
                    s_zx + tl * ESTR + DIN + part * 16);
                float s = 0.f;
#pragma unroll
                for (int q = 0; q < 4; q++) {
                    float4 v = gp[q];
                    s += v.x * v.x + v.y * v.y + v.z * v.z + v.w * v.w;
                }
                s += __shfl_xor_sync(0xffffffffu, s, 1);
                s += __shfl_xor_sync(0xffffffffu, s, 2);
                s += __shfl_xor_sync(0xffffffffu, s, 4);
                s += __shfl_xor_sync(0xffffffffu, s, 8);
                if (part == 0) s_inv2[tl] = rsqrtf(s * (1.f / DIN) + EPS);
            }
            {
#pragma unroll
                for (int kk = 0; kk < 2; kk++) {
                    int kc = warp + kk * 8;     // 0..15
#pragma unroll
                    for (int r = 0; r < 4; r++) {
                        int tt = tb + (r & 1) * 8;
                        int e  = DIN + kc * 16 + 2 * kb + (r >> 1) * 8;
                        float2 v = *reinterpret_cast<const float2*>(s_zx + tt * ESTR + e);
                        int w = kc * 128 + lane * 4 + r;
                        s_zxw[ZIDX(w)] = hcvt(v.x, v.y);
                    }
                }
            }
            __syncthreads();

            // ---- out_proj half (M=16, 2-pass) + residual + fused A-pack --------
            {
                const unsigned* Wf = g_opf + (size_t)blk * (OP_NT * OP_KC * 128);
                float dacc[2][4];
#pragma unroll
                for (int j = 0; j < 2; j++)
#pragma unroll
                    for (int q = 0; q < 4; q++) dacc[j][q] = 0.f;

#pragma unroll 1
                for (int kc = 0; kc < OP_KC; kc++) {
                    uint4 ah = *reinterpret_cast<const uint4*>(
                        s_zxw + ZIDX(kc * 128 + lane * 4));
                    uint4 bf0 = *reinterpret_cast<const uint4*>(
                        Wf + ((size_t)((warp + 0) * OP_KC + kc)) * 128 + lane * 4);
                    uint4 bf1 = *reinterpret_cast<const uint4*>(
                        Wf + ((size_t)((warp + 8) * OP_KC + kc)) * 128 + lane * 4);
                    mma_f16(dacc[0], &ah.x, bf0.x, bf0.y);
                    mma_f16(dacc[1], &ah.x, bf1.x, bf1.y);
                    mma_f16(dacc[0], &ah.x, bf0.z, bf0.w);
                    mma_f16(dacc[1], &ah.x, bf1.z, bf1.w);
                }
                // epilogue: residual into hsT (global t) + next-layer A-pack
#pragma unroll
                for (int j = 0; j < 2; j++) {
                    int n  = warp + j * 8;
                    int d0 = n * 8 + 2 * kb;
                    unsigned wb = (((n >> 1) * 2) * 128) + lane * 4 + 2 * (n & 1);
                    int t0 = m * 16 + tb;
                    float i0 = s_inv2[tb], i1 = s_inv2[tb + 8];
                    float v0 = s_hsT[d0 * TST + t0]           + dacc[j][0] * i0;
                    float v1 = s_hsT[(d0 + 1) * TST + t0]     + dacc[j][1] * i0;
                    float v2 = s_hsT[d0 * TST + t0 + 8]       + dacc[j][2] * i1;
                    float v3 = s_hsT[(d0 + 1) * TST + t0 + 8] + dacc[j][3] * i1;
                    s_hsT[d0 * TST + t0]           = v0;
                    s_hsT[(d0 + 1) * TST + t0]     = v1;
                    s_hsT[d0 * TST + t0 + 8]       = v2;
                    s_hsT[(d0 + 1) * TST + t0 + 8] = v3;
                    if (l == 0) {
                        s_apk[wb + m * 128 + 0] = hcvt(v0, v1);
                        s_apk[wb + m * 128 + 1] = hcvt(v2, v3);
                    }
                }
            }
            __syncthreads();
        } // half
    } // layer

    // ---- final rmsnorm(norm_f) over d (all 32 t) --------------------------------
    {
        float s = 0.f;
#pragma unroll
        for (int q = 0; q < 16; q++) {
            float v = s_hsT[(warp * 16 + q) * TST + lane];
            s += v * v;
        }
        s_red[warp * 32 + lane] = s;
    }
    __syncthreads();
    if (tid < 32) {
        float s = 0.f;
#pragma unroll
        for (int w = 0; w < 8; w++) s += s_red[w * 32 + tid];
        s_inv[tid] = rsqrtf(s * (1.f / DM) + EPS);
    }
    __syncthreads();

    // ---- L-weighted accumulate -> g_A ------------------------------------------
    if (tid < DM) {
        const float* hrow = s_hsT + tid * TST;
        float s = 0.f;
#pragma unroll
        for (int t = 0; t < LSEQ; t++) {
            float wl = olw[dir ? (LSEQ - 1 - t) : t];
            s = fmaf(wl * s_inv[t], hrow[t], s);
        }
        g_A[((size_t)b * 2 + dir) * DM + tid] = s * nfw[dir * DM + tid];
    }
}

extern "C" void kernel_launch(void* const* d_in, const int* in_sizes, int n_in,
                              void* d_out, int out_size) {
    const float* x      = (const float*)d_in[0];
    const float* buffer = (const float*)d_in[1];
    const float* fiw    = (const float*)d_in[2];
    const float* fib    = (const float*)d_in[3];
    const float* bnw    = (const float*)d_in[4];
    const float* ipw    = (const float*)d_in[5];
    const float* cw     = (const float*)d_in[6];
    const float* cb     = (const float*)d_in[7];
    const float* dtb    = (const float*)d_in[8];
    const float* alog   = (const float*)d_in[9];
    const float* Dp     = (const float*)d_in[10];
    const float* mnw    = (const float*)d_in[11];
    const float* opw    = (const float*)d_in[12];
    const float* nfw    = (const float*)d_in[13];
    const float* fow    = (const float*)d_in[14];
    const float* fob    = (const float*)d_in[15];
    const float* olw    = (const float*)d_in[16];
    const float* olb    = (const float*)d_in[17];
    float* out = (float*)d_out;

    int B = in_sizes[0] / CIN;   // 1024
    size_t smem_bytes = (size_t)SMEM_FLOATS * sizeof(float);

    cudaFuncSetAttribute(mamba_actor_kernel,
                         cudaFuncAttributeMaxDynamicSharedMemorySize,
                         (int)smem_bytes);

    int prep_total = IPF_N + OPF_N + FIF_N;
    prep_weights<<<(prep_total + 255) / 256, 256>>>(ipw, bnw, opw, mnw, fiw);

    mamba_actor_kernel<<<2 * B, NT, smem_bytes>>>(
        x, buffer, fib, cw, cb, dtb, alog,
        Dp, nfw, olw, out);

    finalize_kernel<<<(B * COUT + 255) / 256, 256>>>(fow, fob, olw, olb, out, B);
}